// round 6
// baseline (speedup 1.0000x reference)
#include <cuda_runtime.h>
#include <cuda_bf16.h>
#include <math.h>

#define BB 16
#define TE 128
#define TD 128
#define HH 256

// Scratch (no allocation allowed -> __device__ globals)
__device__ float g_enc_o[BB * TE * HH];   // orthogonalized encoder [b][t][h]
__device__ float g_was[BB * TE * HH];     // enc_o @ W_a              [b][e][h]
__device__ float g_uah[BB * TD * HH];     // dec   @ U_a              [b][d][h]
__device__ float g_dump[BB * TD * HH];    // fallback sink if harness wants only one output

// ---------------------------------------------------------------------------
// K1: Gram-Schmidt-style ortho pass.
//   x[t] = enc[b][t][h]; s[t] = sum_{j<t} x[j];  out = x - ((x*s)/(x*x))*x
// One thread per (b,h); block per b, coalesced loads, register double-buffer.
// ---------------------------------------------------------------------------
__global__ void k_ortho(const float* __restrict__ enc) {
    const int b = blockIdx.x;
    const int h = threadIdx.x;
    const float* src = enc + (size_t)b * TE * HH + h;
    float* dst = g_enc_o + (size_t)b * TE * HH + h;

    float s = 0.0f;
    float cur[8], nxt[8];
#pragma unroll
    for (int i = 0; i < 8; i++) cur[i] = src[i * HH];

    for (int tc = 0; tc < 16; tc++) {
        if (tc < 15) {
#pragma unroll
            for (int i = 0; i < 8; i++) nxt[i] = src[((tc + 1) * 8 + i) * HH];
        }
#pragma unroll
        for (int i = 0; i < 8; i++) {
            float x = cur[i];
            float q = (x * s) / (x * x);   // IEEE div; t=0 -> s=0 -> q=0 -> out=x
            dst[(tc * 8 + i) * HH] = x - q * x;
            s += x;
        }
#pragma unroll
        for (int i = 0; i < 8; i++) cur[i] = nxt[i];
    }
}

// ---------------------------------------------------------------------------
// K2: two SGEMMs, C[2048,256] = A[2048,256] * W[256,256]
//   z==0: was = enc_o @ W_a        z==1: uah = dec @ U_a
// 64x64 tile, BK=16, 256 threads, 4x4 microtile, k-major smem (vector LDS).
// ---------------------------------------------------------------------------
__global__ void k_gemm(const float* __restrict__ dec,
                       const float* __restrict__ Wa,
                       const float* __restrict__ Ua) {
    const float* A;
    const float* W;
    float* C;
    if (blockIdx.z == 0) { A = g_enc_o; W = Wa; C = g_was; }
    else                 { A = dec;     W = Ua; C = g_uah; }

    __shared__ float As[16][64];   // [k][row]
    __shared__ float Bs[16][64];   // [k][col]

    const int tid = threadIdx.x;
    const int tx = tid & 15;        // col group
    const int ty = tid >> 4;        // row group
    const int row0 = blockIdx.y * 64;
    const int col0 = blockIdx.x * 64;

    // global->smem load indices
    const int ar = tid >> 2;          // 0..63 (row within tile)
    const int ak = (tid & 3) * 4;     // 0,4,8,12 (k offset)
    const int bk = tid >> 4;          // 0..15 (k row)
    const int bc = (tid & 15) * 4;    // 0..60 (col offset)

    float acc[4][4];
#pragma unroll
    for (int i = 0; i < 4; i++)
#pragma unroll
        for (int j = 0; j < 4; j++) acc[i][j] = 0.0f;

    for (int kk = 0; kk < HH; kk += 16) {
        float4 av = *(const float4*)&A[(size_t)(row0 + ar) * HH + kk + ak];
        float4 bv = *(const float4*)&W[(size_t)(kk + bk) * HH + col0 + bc];
        As[ak + 0][ar] = av.x;
        As[ak + 1][ar] = av.y;
        As[ak + 2][ar] = av.z;
        As[ak + 3][ar] = av.w;
        *(float4*)&Bs[bk][bc] = bv;
        __syncthreads();

#pragma unroll
        for (int k = 0; k < 16; k++) {
            float4 a = *(const float4*)&As[k][ty * 4];
            float4 b = *(const float4*)&Bs[k][tx * 4];
            acc[0][0] = fmaf(a.x, b.x, acc[0][0]);
            acc[0][1] = fmaf(a.x, b.y, acc[0][1]);
            acc[0][2] = fmaf(a.x, b.z, acc[0][2]);
            acc[0][3] = fmaf(a.x, b.w, acc[0][3]);
            acc[1][0] = fmaf(a.y, b.x, acc[1][0]);
            acc[1][1] = fmaf(a.y, b.y, acc[1][1]);
            acc[1][2] = fmaf(a.y, b.z, acc[1][2]);
            acc[1][3] = fmaf(a.y, b.w, acc[1][3]);
            acc[2][0] = fmaf(a.z, b.x, acc[2][0]);
            acc[2][1] = fmaf(a.z, b.y, acc[2][1]);
            acc[2][2] = fmaf(a.z, b.z, acc[2][2]);
            acc[2][3] = fmaf(a.z, b.w, acc[2][3]);
            acc[3][0] = fmaf(a.w, b.x, acc[3][0]);
            acc[3][1] = fmaf(a.w, b.y, acc[3][1]);
            acc[3][2] = fmaf(a.w, b.z, acc[3][2]);
            acc[3][3] = fmaf(a.w, b.w, acc[3][3]);
        }
        __syncthreads();
    }

#pragma unroll
    for (int i = 0; i < 4; i++) {
        float4 v = make_float4(acc[i][0], acc[i][1], acc[i][2], acc[i][3]);
        *(float4*)&C[(size_t)(row0 + ty * 4 + i) * HH + col0 + tx * 4] = v;
    }
}

// ---------------------------------------------------------------------------
// K3: fused energy -> softmax -> context.
// Block = (b, 4 decoder rows). 128 threads = 4 d-warps x 32 e-lanes.
//   energy[d][e] = sum_h tanh(was[b,e,h] + uah[b,d,h]) * V[h]
//   p = softmax_e(energy);  c[d,h] = sum_e p[e] * enc_o[b,e,h]
// tanh(x) = 1 - 2/(exp(2x)+1): EX2 + RCP (accurate to ~2e-7, saturates right).
// ---------------------------------------------------------------------------
#define DT 4
#define ET 32

__global__ void k_attn(const float* __restrict__ Va,
                       float* __restrict__ c_out_p,
                       float* __restrict__ e_out_p) {
    float* c_out = c_out_p ? c_out_p : g_dump;
    float* e_out = e_out_p ? e_out_p : g_dump;

    const int b = blockIdx.x >> 5;          // / (TD/DT = 32)
    const int d0 = (blockIdx.x & 31) * DT;
    const int tid = threadIdx.x;            // 128 threads

    __shared__ float u_s[DT][HH];           // 4 KB
    __shared__ float V_s[HH];               // 1 KB
    __shared__ float was_s[ET][HH + 1];     // pad -> bank-conflict free
    __shared__ float p_s[DT][TE];           // 2 KB

    // load uah rows for the DT decoder positions (float4, coalesced)
    for (int i = tid; i < DT * (HH / 4); i += 128) {
        int d = i / (HH / 4);
        int c = (i % (HH / 4)) * 4;
        *(float4*)&u_s[d][c] =
            *(const float4*)&g_uah[(size_t)(b * TD + d0 + d) * HH + c];
    }
    if (tid < HH / 4) {
        *(float4*)&V_s[tid * 4] = *(const float4*)&Va[tid * 4];
    }
    __syncthreads();

    const int d = tid >> 5;       // 0..3
    const int el = tid & 31;      // 0..31

    for (int ec = 0; ec < TE / ET; ec++) {
        // stage was[b, ec*32 .. +32, :] into smem
        for (int i = tid; i < ET * (HH / 4); i += 128) {
            int r = i >> 6;
            int c = (i & 63) * 4;
            float4 v = *(const float4*)&g_was[(size_t)(b * TE + ec * ET + r) * HH + c];
            was_s[r][c + 0] = v.x;
            was_s[r][c + 1] = v.y;
            was_s[r][c + 2] = v.z;
            was_s[r][c + 3] = v.w;
        }
        __syncthreads();

        const float* wrow = &was_s[el][0];
        const float* urow = &u_s[d][0];
        float acc = 0.0f;
#pragma unroll 8
        for (int h = 0; h < HH; h++) {
            float x = wrow[h] + urow[h];
            float z = __expf(x + x);                       // EX2 (saturates to inf/0 -> tanh = +-1)
            float th = 1.0f - __fdividef(2.0f, z + 1.0f);  // RCP
            acc = fmaf(th, V_s[h], acc);
        }
        p_s[d][ec * ET + el] = acc;
        __syncthreads();
    }

    // softmax: warp w handles decoder row d0+w
    {
        const int w = tid >> 5;
        const int l = tid & 31;
        float vals[4];
#pragma unroll
        for (int j = 0; j < 4; j++) vals[j] = p_s[w][l + j * 32];
        float m = fmaxf(fmaxf(vals[0], vals[1]), fmaxf(vals[2], vals[3]));
#pragma unroll
        for (int off = 16; off > 0; off >>= 1)
            m = fmaxf(m, __shfl_xor_sync(0xFFFFFFFFu, m, off));
        float s = 0.0f;
#pragma unroll
        for (int j = 0; j < 4; j++) { vals[j] = __expf(vals[j] - m); s += vals[j]; }
#pragma unroll
        for (int off = 16; off > 0; off >>= 1)
            s += __shfl_xor_sync(0xFFFFFFFFu, s, off);
        float inv = 1.0f / s;
#pragma unroll
        for (int j = 0; j < 4; j++) {
            float p = vals[j] * inv;
            p_s[w][l + j * 32] = p;
            e_out[(size_t)(b * TD + d0 + w) * TE + l + j * 32] = p;
        }
    }
    __syncthreads();

    // context: thread owns columns h = tid and tid+128
    {
        float acc0[DT], acc1[DT];
#pragma unroll
        for (int dd = 0; dd < DT; dd++) { acc0[dd] = 0.0f; acc1[dd] = 0.0f; }
        const float* encb = g_enc_o + (size_t)b * TE * HH;
#pragma unroll 4
        for (int e = 0; e < TE; e++) {
            float v0 = encb[(size_t)e * HH + tid];
            float v1 = encb[(size_t)e * HH + tid + 128];
#pragma unroll
            for (int dd = 0; dd < DT; dd++) {
                float pp = p_s[dd][e];
                acc0[dd] = fmaf(pp, v0, acc0[dd]);
                acc1[dd] = fmaf(pp, v1, acc1[dd]);
            }
        }
#pragma unroll
        for (int dd = 0; dd < DT; dd++) {
            c_out[(size_t)(b * TD + d0 + dd) * HH + tid]       = acc0[dd];
            c_out[(size_t)(b * TD + d0 + dd) * HH + tid + 128] = acc1[dd];
        }
    }
}

// ---------------------------------------------------------------------------
// Launch: ortho -> (2x GEMM in one kernel) -> fused attention.
// Outputs: reference returns (c_outputs [B,TD,H], e_outputs [B,TD,TE]),
// written back-to-back into d_out in tuple order.
// ---------------------------------------------------------------------------
extern "C" void kernel_launch(void* const* d_in, const int* in_sizes, int n_in,
                              void* d_out, int out_size) {
    const float* enc = (const float*)d_in[0];
    const float* dec = (const float*)d_in[1];
    const float* Wa  = (const float*)d_in[2];
    const float* Ua  = (const float*)d_in[3];
    const float* Va  = (const float*)d_in[4];
    (void)in_sizes; (void)n_in;

    const int size_c = BB * TD * HH;   // 524288
    const int size_e = BB * TD * TE;   // 262144

    float* c_out;
    float* e_out;
    if (out_size >= size_c + size_e) {
        c_out = (float*)d_out;
        e_out = (float*)d_out + size_c;
    } else if (out_size == size_c) {
        c_out = (float*)d_out;
        e_out = nullptr;               // kernel redirects to g_dump
    } else {
        c_out = nullptr;
        e_out = (float*)d_out;
    }

    k_ortho<<<BB, HH>>>(enc);
    k_gemm<<<dim3(HH / 64, (BB * TE) / 64, 2), 256>>>(dec, Wa, Ua);
    k_attn<<<BB * (TD / DT), 128>>>(Va, c_out, e_out);
}

// round 10
// speedup vs baseline: 1.0307x; 1.0307x over previous
#include <cuda_runtime.h>
#include <cuda_bf16.h>
#include <math.h>

#define BB 16
#define TE 128
#define TD 128
#define HH 256

// Scratch (no allocation allowed -> __device__ globals)
__device__ float g_enc_o[BB * TE * HH];   // orthogonalized encoder [b][t][h]
__device__ float g_was[BB * TE * HH];     // enc_o @ W_a              [b][e][h]
__device__ float g_uah[BB * TD * HH];     // dec   @ U_a              [b][d][h]
__device__ float g_dump[BB * TD * HH];    // fallback sink if harness wants only one output

// ---------------------------------------------------------------------------
// packed f32x2 helpers (ptxas never auto-fuses FFMA2; PTX-only path)
// ---------------------------------------------------------------------------
__device__ __forceinline__ unsigned long long pack2(float lo, float hi) {
    unsigned long long r;
    asm("mov.b64 %0, {%1, %2};" : "=l"(r) : "f"(lo), "f"(hi));
    return r;
}
__device__ __forceinline__ void unpack2(unsigned long long v, float& lo, float& hi) {
    asm("mov.b64 {%0, %1}, %2;" : "=f"(lo), "=f"(hi) : "l"(v));
}
__device__ __forceinline__ unsigned long long ffma2(unsigned long long a,
                                                    unsigned long long b,
                                                    unsigned long long c) {
    unsigned long long d;
    asm("fma.rn.f32x2 %0, %1, %2, %3;" : "=l"(d) : "l"(a), "l"(b), "l"(c));
    return d;
}

// ---------------------------------------------------------------------------
// K1: Gram-Schmidt-style ortho pass — warp-segmented scan version.
//   s[t] = cumsum_incl[t] - x[t] (as in the reference);  out = x - ((x*s)/(x*x))*x
// Block = (b, 32 h-columns), 256 threads. Stage [128t][32h] tile through smem
// (transposed, padded -> conflict-free), warp w scans h-columns {w, w+8, w+16, w+24}
// with shfl_up inclusive scans over 4 chunks of 32 timesteps + running carry.
// 128 blocks x 256 thr = 32k threads (vs 4k before) -> latency hidden.
// ---------------------------------------------------------------------------
__global__ void k_ortho(const float* __restrict__ enc) {
    const int b  = blockIdx.y;
    const int h0 = blockIdx.x * 32;
    const int tid = threadIdx.x;            // 256

    __shared__ float s[32][TE + 1];         // [h_local][t], stride 129 -> conflict-free

    const float* src = enc + (size_t)b * TE * HH + h0;

    // coalesced load: warp covers 32 consecutive h for a fixed t
#pragma unroll
    for (int i = 0; i < 16; i++) {
        int idx = tid + i * 256;
        int t = idx >> 5, hl = idx & 31;
        s[hl][t] = src[(size_t)t * HH + hl];
    }
    __syncthreads();

    const int w = tid >> 5, lane = tid & 31;
#pragma unroll
    for (int j = 0; j < 4; j++) {
        const int hl = w + j * 8;
        float carry = 0.0f;
#pragma unroll
        for (int c = 0; c < 4; c++) {
            float v = s[hl][c * 32 + lane];
            float incl = v;
#pragma unroll
            for (int off = 1; off < 32; off <<= 1) {
                float n = __shfl_up_sync(0xFFFFFFFFu, incl, off);
                if (lane >= off) incl += n;
            }
            float st = carry + (incl - v);      // exclusive sum, reference-style
            float x = v;
            float q = (x * st) / (x * x);       // IEEE div; t=0 -> st=0 -> q=0 -> out=x
            s[hl][c * 32 + lane] = x - q * x;
            carry += __shfl_sync(0xFFFFFFFFu, incl, 31);
        }
    }
    __syncthreads();

    float* dst = g_enc_o + (size_t)b * TE * HH + h0;
#pragma unroll
    for (int i = 0; i < 16; i++) {
        int idx = tid + i * 256;
        int t = idx >> 5, hl = idx & 31;
        dst[(size_t)t * HH + hl] = s[hl][t];
    }
}

// ---------------------------------------------------------------------------
// K2: two SGEMMs, C[2048,256] = A[2048,256] * W[256,256]
//   z==0: was = enc_o @ W_a        z==1: uah = dec @ U_a
// 64x64 tile, BK=16, 256 threads, 4x4 microtile. Inner product via packed
// fma.rn.f32x2 (8 FMA2/k instead of 16 FFMA/k -> halves fma-pipe occupancy).
// ---------------------------------------------------------------------------
__global__ void k_gemm(const float* __restrict__ dec,
                       const float* __restrict__ Wa,
                       const float* __restrict__ Ua) {
    const float* A;
    const float* W;
    float* C;
    if (blockIdx.z == 0) { A = g_enc_o; W = Wa; C = g_was; }
    else                 { A = dec;     W = Ua; C = g_uah; }

    __shared__ float As[16][64];   // [k][row]
    __shared__ float Bs[16][64];   // [k][col]

    const int tid = threadIdx.x;
    const int tx = tid & 15;        // col group
    const int ty = tid >> 4;        // row group
    const int row0 = blockIdx.y * 64;
    const int col0 = blockIdx.x * 64;

    const int ar = tid >> 2;          // 0..63 (row within tile)
    const int ak = (tid & 3) * 4;     // 0,4,8,12 (k offset)
    const int bk = tid >> 4;          // 0..15 (k row)
    const int bc = (tid & 15) * 4;    // 0..60 (col offset)

    unsigned long long acc2[4][2];
#pragma unroll
    for (int i = 0; i < 4; i++) { acc2[i][0] = 0ull; acc2[i][1] = 0ull; }

    for (int kk = 0; kk < HH; kk += 16) {
        float4 av = *(const float4*)&A[(size_t)(row0 + ar) * HH + kk + ak];
        float4 bv = *(const float4*)&W[(size_t)(kk + bk) * HH + col0 + bc];
        As[ak + 0][ar] = av.x;
        As[ak + 1][ar] = av.y;
        As[ak + 2][ar] = av.z;
        As[ak + 3][ar] = av.w;
        *(float4*)&Bs[bk][bc] = bv;
        __syncthreads();

#pragma unroll
        for (int k = 0; k < 16; k++) {
            float4 a = *(const float4*)&As[k][ty * 4];
            float4 b = *(const float4*)&Bs[k][tx * 4];
            unsigned long long b01 = pack2(b.x, b.y);
            unsigned long long b23 = pack2(b.z, b.w);
            unsigned long long a0 = pack2(a.x, a.x);
            unsigned long long a1 = pack2(a.y, a.y);
            unsigned long long a2 = pack2(a.z, a.z);
            unsigned long long a3 = pack2(a.w, a.w);
            acc2[0][0] = ffma2(a0, b01, acc2[0][0]);
            acc2[0][1] = ffma2(a0, b23, acc2[0][1]);
            acc2[1][0] = ffma2(a1, b01, acc2[1][0]);
            acc2[1][1] = ffma2(a1, b23, acc2[1][1]);
            acc2[2][0] = ffma2(a2, b01, acc2[2][0]);
            acc2[2][1] = ffma2(a2, b23, acc2[2][1]);
            acc2[3][0] = ffma2(a3, b01, acc2[3][0]);
            acc2[3][1] = ffma2(a3, b23, acc2[3][1]);
        }
        __syncthreads();
    }

#pragma unroll
    for (int i = 0; i < 4; i++) {
        float4 v;
        unpack2(acc2[i][0], v.x, v.y);
        unpack2(acc2[i][1], v.z, v.w);
        *(float4*)&C[(size_t)(row0 + ty * 4 + i) * HH + col0 + tx * 4] = v;
    }
}

// ---------------------------------------------------------------------------
// K3: fused energy -> softmax -> context.
// Block = (b, 4 decoder rows). 128 threads = 4 d-warps x 32 e-lanes.
//   energy[d][e] = sum_h tanh(was[b,e,h] + uah[b,d,h]) * V[h]
// tanh via native MUFU tanh.approx.f32 (1 MUFU/elem instead of 2 -> halves
// the MUFU bound that dominates this kernel).
// ---------------------------------------------------------------------------
#define DT 4
#define ET 32

__global__ void k_attn(const float* __restrict__ Va,
                       float* __restrict__ c_out_p,
                       float* __restrict__ e_out_p) {
    float* c_out = c_out_p ? c_out_p : g_dump;
    float* e_out = e_out_p ? e_out_p : g_dump;

    const int b = blockIdx.x >> 5;          // / (TD/DT = 32)
    const int d0 = (blockIdx.x & 31) * DT;
    const int tid = threadIdx.x;            // 128 threads

    __shared__ float u_s[DT][HH];           // 4 KB
    __shared__ float V_s[HH];               // 1 KB
    __shared__ float was_s[ET][HH + 1];     // pad -> bank-conflict free
    __shared__ float p_s[DT][TE];           // 2 KB

    for (int i = tid; i < DT * (HH / 4); i += 128) {
        int d = i / (HH / 4);
        int c = (i % (HH / 4)) * 4;
        *(float4*)&u_s[d][c] =
            *(const float4*)&g_uah[(size_t)(b * TD + d0 + d) * HH + c];
    }
    if (tid < HH / 4) {
        *(float4*)&V_s[tid * 4] = *(const float4*)&Va[tid * 4];
    }
    __syncthreads();

    const int d = tid >> 5;       // 0..3
    const int el = tid & 31;      // 0..31

    for (int ec = 0; ec < TE / ET; ec++) {
        // stage was[b, ec*32 .. +32, :] into smem
        for (int i = tid; i < ET * (HH / 4); i += 128) {
            int r = i >> 6;
            int c = (i & 63) * 4;
            float4 v = *(const float4*)&g_was[(size_t)(b * TE + ec * ET + r) * HH + c];
            was_s[r][c + 0] = v.x;
            was_s[r][c + 1] = v.y;
            was_s[r][c + 2] = v.z;
            was_s[r][c + 3] = v.w;
        }
        __syncthreads();

        const float* wrow = &was_s[el][0];
        const float* urow = &u_s[d][0];
        float acc = 0.0f;
#pragma unroll 8
        for (int h = 0; h < HH; h++) {
            float x = wrow[h] + urow[h];
            float th;
            asm("tanh.approx.f32 %0, %1;" : "=f"(th) : "f"(x));  // 1 MUFU
            acc = fmaf(th, V_s[h], acc);
        }
        p_s[d][ec * ET + el] = acc;
        __syncthreads();
    }

    // softmax: warp w handles decoder row d0+w
    {
        const int w = tid >> 5;
        const int l = tid & 31;
        float vals[4];
#pragma unroll
        for (int j = 0; j < 4; j++) vals[j] = p_s[w][l + j * 32];
        float m = fmaxf(fmaxf(vals[0], vals[1]), fmaxf(vals[2], vals[3]));
#pragma unroll
        for (int off = 16; off > 0; off >>= 1)
            m = fmaxf(m, __shfl_xor_sync(0xFFFFFFFFu, m, off));
        float s = 0.0f;
#pragma unroll
        for (int j = 0; j < 4; j++) { vals[j] = __expf(vals[j] - m); s += vals[j]; }
#pragma unroll
        for (int off = 16; off > 0; off >>= 1)
            s += __shfl_xor_sync(0xFFFFFFFFu, s, off);
        float inv = 1.0f / s;
#pragma unroll
        for (int j = 0; j < 4; j++) {
            float p = vals[j] * inv;
            p_s[w][l + j * 32] = p;
            e_out[(size_t)(b * TD + d0 + w) * TE + l + j * 32] = p;
        }
    }
    __syncthreads();

    // context: thread owns columns h = tid and tid+128
    {
        float acc0[DT], acc1[DT];
#pragma unroll
        for (int dd = 0; dd < DT; dd++) { acc0[dd] = 0.0f; acc1[dd] = 0.0f; }
        const float* encb = g_enc_o + (size_t)b * TE * HH;
#pragma unroll 4
        for (int e = 0; e < TE; e++) {
            float v0 = encb[(size_t)e * HH + tid];
            float v1 = encb[(size_t)e * HH + tid + 128];
#pragma unroll
            for (int dd = 0; dd < DT; dd++) {
                float pp = p_s[dd][e];
                acc0[dd] = fmaf(pp, v0, acc0[dd]);
                acc1[dd] = fmaf(pp, v1, acc1[dd]);
            }
        }
#pragma unroll
        for (int dd = 0; dd < DT; dd++) {
            c_out[(size_t)(b * TD + d0 + dd) * HH + tid]       = acc0[dd];
            c_out[(size_t)(b * TD + d0 + dd) * HH + tid + 128] = acc1[dd];
        }
    }
}

// ---------------------------------------------------------------------------
// Launch: ortho -> (2x GEMM in one kernel) -> fused attention.
// Outputs: (c_outputs [B,TD,H], e_outputs [B,TD,TE]) back-to-back in d_out.
// ---------------------------------------------------------------------------
extern "C" void kernel_launch(void* const* d_in, const int* in_sizes, int n_in,
                              void* d_out, int out_size) {
    const float* enc = (const float*)d_in[0];
    const float* dec = (const float*)d_in[1];
    const float* Wa  = (const float*)d_in[2];
    const float* Ua  = (const float*)d_in[3];
    const float* Va  = (const float*)d_in[4];
    (void)in_sizes; (void)n_in;

    const int size_c = BB * TD * HH;   // 524288
    const int size_e = BB * TD * TE;   // 262144

    float* c_out;
    float* e_out;
    if (out_size >= size_c + size_e) {
        c_out = (float*)d_out;
        e_out = (float*)d_out + size_c;
    } else if (out_size == size_c) {
        c_out = (float*)d_out;
        e_out = nullptr;               // kernel redirects to g_dump
    } else {
        c_out = nullptr;
        e_out = (float*)d_out;
    }

    k_ortho<<<dim3(HH / 32, BB), 256>>>(enc);
    k_gemm<<<dim3(HH / 64, (BB * TE) / 64, 2), 256>>>(dec, Wa, Ua);
    k_attn<<<BB * (TD / DT), 128>>>(Va, c_out, e_out);
}

// round 13
// speedup vs baseline: 1.4646x; 1.4210x over previous
#include <cuda_runtime.h>
#include <cuda_bf16.h>
#include <math.h>

#define BB 16
#define TE 128
#define TD 128
#define HH 256

// Scratch (no allocation allowed -> __device__ globals)
__device__ float g_enc_o[BB * TE * HH];   // orthogonalized encoder [b][t][h]
__device__ float g_was[BB * TE * HH];     // enc_o @ W_a              [b][e][h]
__device__ float g_uah[BB * TD * HH];     // dec   @ U_a              [b][d][h]
__device__ float g_dump[BB * TD * HH];    // fallback sink if harness wants only one output

// ---------------------------------------------------------------------------
// K1: Gram-Schmidt-style ortho pass — one warp per (b,h) scan.
//   s[t] = cumsum_incl[t] - x[t] (reference math);  out = x - ((x*s)/(x*x))*x
// Block = (b, 8 h-columns), 256 threads = 8 warps, warp w owns column h0+w.
// 512 blocks -> every SM busy (vs 128 blocks before, occ 12.6%).
// ---------------------------------------------------------------------------
__global__ void k_ortho(const float* __restrict__ enc) {
    const int b  = blockIdx.y;
    const int h0 = blockIdx.x * 8;
    const int tid = threadIdx.x;            // 256

    __shared__ float s[8][TE + 1];          // [h_local][t], stride 129 -> conflict-free

    const float* src = enc + (size_t)b * TE * HH + h0;

    // coalesced-enough load: 8 consecutive h per t = one 32B sector per row
#pragma unroll
    for (int i = 0; i < 4; i++) {
        int idx = tid + i * 256;
        int t = idx >> 3, hl = idx & 7;
        s[hl][t] = src[(size_t)t * HH + hl];
    }
    __syncthreads();

    const int w = tid >> 5, lane = tid & 31;
    {
        float carry = 0.0f;
#pragma unroll
        for (int c = 0; c < 4; c++) {
            float v = s[w][c * 32 + lane];
            float incl = v;
#pragma unroll
            for (int off = 1; off < 32; off <<= 1) {
                float n = __shfl_up_sync(0xFFFFFFFFu, incl, off);
                if (lane >= off) incl += n;
            }
            float st = carry + (incl - v);      // exclusive sum, reference-style
            float q = (v * st) / (v * v);       // IEEE div; t=0 -> st=0 -> q=0 -> out=v
            s[w][c * 32 + lane] = v - q * v;
            carry += __shfl_sync(0xFFFFFFFFu, incl, 31);
        }
    }
    __syncthreads();

    float* dst = g_enc_o + (size_t)b * TE * HH + h0;
#pragma unroll
    for (int i = 0; i < 4; i++) {
        int idx = tid + i * 256;
        int t = idx >> 3, hl = idx & 7;
        dst[(size_t)t * HH + hl] = s[hl][t];
    }
}

// ---------------------------------------------------------------------------
// K2: two SGEMMs, C[2048,256] = A[2048,256] * W[256,256]  (plain FFMA — the
// fma.rn.f32x2 experiment regressed; reverted).
//   z==0: was = enc_o @ W_a        z==1: uah = dec @ U_a
// 64x64 tile, BK=16, 256 threads, 4x4 microtile, k-major smem (vector LDS).
// ---------------------------------------------------------------------------
__global__ void k_gemm(const float* __restrict__ dec,
                       const float* __restrict__ Wa,
                       const float* __restrict__ Ua) {
    const float* A;
    const float* W;
    float* C;
    if (blockIdx.z == 0) { A = g_enc_o; W = Wa; C = g_was; }
    else                 { A = dec;     W = Ua; C = g_uah; }

    __shared__ float As[16][64];   // [k][row]
    __shared__ float Bs[16][64];   // [k][col]

    const int tid = threadIdx.x;
    const int tx = tid & 15;        // col group
    const int ty = tid >> 4;        // row group
    const int row0 = blockIdx.y * 64;
    const int col0 = blockIdx.x * 64;

    const int ar = tid >> 2;          // 0..63 (row within tile)
    const int ak = (tid & 3) * 4;     // 0,4,8,12 (k offset)
    const int bk = tid >> 4;          // 0..15 (k row)
    const int bc = (tid & 15) * 4;    // 0..60 (col offset)

    float acc[4][4];
#pragma unroll
    for (int i = 0; i < 4; i++)
#pragma unroll
        for (int j = 0; j < 4; j++) acc[i][j] = 0.0f;

    for (int kk = 0; kk < HH; kk += 16) {
        float4 av = *(const float4*)&A[(size_t)(row0 + ar) * HH + kk + ak];
        float4 bv = *(const float4*)&W[(size_t)(kk + bk) * HH + col0 + bc];
        As[ak + 0][ar] = av.x;
        As[ak + 1][ar] = av.y;
        As[ak + 2][ar] = av.z;
        As[ak + 3][ar] = av.w;
        *(float4*)&Bs[bk][bc] = bv;
        __syncthreads();

#pragma unroll
        for (int k = 0; k < 16; k++) {
            float4 a = *(const float4*)&As[k][ty * 4];
            float4 b = *(const float4*)&Bs[k][tx * 4];
            acc[0][0] = fmaf(a.x, b.x, acc[0][0]);
            acc[0][1] = fmaf(a.x, b.y, acc[0][1]);
            acc[0][2] = fmaf(a.x, b.z, acc[0][2]);
            acc[0][3] = fmaf(a.x, b.w, acc[0][3]);
            acc[1][0] = fmaf(a.y, b.x, acc[1][0]);
            acc[1][1] = fmaf(a.y, b.y, acc[1][1]);
            acc[1][2] = fmaf(a.y, b.z, acc[1][2]);
            acc[1][3] = fmaf(a.y, b.w, acc[1][3]);
            acc[2][0] = fmaf(a.z, b.x, acc[2][0]);
            acc[2][1] = fmaf(a.z, b.y, acc[2][1]);
            acc[2][2] = fmaf(a.z, b.z, acc[2][2]);
            acc[2][3] = fmaf(a.z, b.w, acc[2][3]);
            acc[3][0] = fmaf(a.w, b.x, acc[3][0]);
            acc[3][1] = fmaf(a.w, b.y, acc[3][1]);
            acc[3][2] = fmaf(a.w, b.z, acc[3][2]);
            acc[3][3] = fmaf(a.w, b.w, acc[3][3]);
        }
        __syncthreads();
    }

#pragma unroll
    for (int i = 0; i < 4; i++) {
        float4 v = make_float4(acc[i][0], acc[i][1], acc[i][2], acc[i][3]);
        *(float4*)&C[(size_t)(row0 + ty * 4 + i) * HH + col0 + tx * 4] = v;
    }
}

// ---------------------------------------------------------------------------
// K3: fused energy -> softmax -> context.  256 threads = 8 warps.
// Warp w = (d = w>>1, h-half = w&1): all 8 warps consume the SAME staged
// 32-e-row tile; each computes a 128-h PARTIAL dot, combined at softmax.
//   -> 2x occupancy vs the old 128-thread version (28 warps/SM).
// was staged TRANSPOSED [h][e+pad]: lane el reads was_t[h][el] = consecutive
// addresses, conflict-free single-wavefront LDS; u_s/V_s are broadcasts.
//   energy[d][e] = sum_h tanh(was[b,e,h] + uah[b,d,h]) * V[h]
// ---------------------------------------------------------------------------
#define DT 4
#define ET 32

__global__ void __launch_bounds__(256, 4) k_attn(const float* __restrict__ Va,
                                                 float* __restrict__ c_out_p,
                                                 float* __restrict__ e_out_p) {
    float* c_out = c_out_p ? c_out_p : g_dump;
    float* e_out = e_out_p ? e_out_p : g_dump;

    const int b = blockIdx.x >> 5;          // / (TD/DT = 32)
    const int d0 = (blockIdx.x & 31) * DT;
    const int tid = threadIdx.x;            // 256 threads

    __shared__ float u_s[DT][HH];           // 4 KB
    __shared__ float V_s[HH];               // 1 KB
    __shared__ float was_t[HH][ET + 1];     // 33 KB, transposed, pad -> conflict-free
    __shared__ float part[2][DT][TE];       // 4 KB  (h-half partials; [0] reused for p)

    // load uah rows: exactly one float4 per thread
    {
        int d = tid >> 6;                   // 0..3
        int c = (tid & 63) * 4;             // 0..252
        *(float4*)&u_s[d][c] =
            *(const float4*)&g_uah[(size_t)(b * TD + d0 + d) * HH + c];
    }
    if (tid < HH / 4) {
        *(float4*)&V_s[tid * 4] = *(const float4*)&Va[tid * 4];
    }
    __syncthreads();

    const int w = tid >> 5;       // warp 0..7
    const int el = tid & 31;      // e-lane
    const int d = w >> 1;         // 0..3
    const int hbase = (w & 1) * 128;

    for (int ec = 0; ec < TE / ET; ec++) {
        // stage was[b, ec*32 .. +32, :] transposed into smem.
        // global read: consecutive tid -> consecutive h (coalesced);
        // smem write: stride ET+1=33 -> conflict-free.
#pragma unroll
        for (int i = 0; i < ET * HH / 256; i++) {
            int idx = tid + i * 256;
            int e = idx >> 8;               // 0..31
            int h = idx & 255;
            was_t[h][e] = g_was[(size_t)(b * TE + ec * ET + e) * HH + h];
        }
        __syncthreads();

        float acc = 0.0f;
        const float* urow = &u_s[d][hbase];
        const float* vrow = &V_s[hbase];
#pragma unroll 8
        for (int hh = 0; hh < 128; hh++) {
            float x = was_t[hbase + hh][el] + urow[hh];
            float th;
            asm("tanh.approx.f32 %0, %1;" : "=f"(th) : "f"(x));  // 1 MUFU
            acc = fmaf(th, vrow[hh], acc);
        }
        part[w & 1][d][ec * ET + el] = acc;
        __syncthreads();
    }

    // softmax: warps 0-3, warp wr handles decoder row d0+wr
    if (w < 4) {
        const int l = el;
        float vals[4];
#pragma unroll
        for (int j = 0; j < 4; j++)
            vals[j] = part[0][w][l + j * 32] + part[1][w][l + j * 32];
        float m = fmaxf(fmaxf(vals[0], vals[1]), fmaxf(vals[2], vals[3]));
#pragma unroll
        for (int off = 16; off > 0; off >>= 1)
            m = fmaxf(m, __shfl_xor_sync(0xFFFFFFFFu, m, off));
        float s = 0.0f;
#pragma unroll
        for (int j = 0; j < 4; j++) { vals[j] = __expf(vals[j] - m); s += vals[j]; }
#pragma unroll
        for (int off = 16; off > 0; off >>= 1)
            s += __shfl_xor_sync(0xFFFFFFFFu, s, off);
        float inv = 1.0f / s;
#pragma unroll
        for (int j = 0; j < 4; j++) {
            float p = vals[j] * inv;
            part[0][w][l + j * 32] = p;
            e_out[(size_t)(b * TD + d0 + w) * TE + l + j * 32] = p;
        }
    }
    __syncthreads();

    // context: thread owns column h = tid (256 threads = all of HH)
    {
        float acc[DT];
#pragma unroll
        for (int dd = 0; dd < DT; dd++) acc[dd] = 0.0f;
        const float* encb = g_enc_o + (size_t)b * TE * HH;
#pragma unroll 4
        for (int e = 0; e < TE; e++) {
            float v = encb[(size_t)e * HH + tid];
#pragma unroll
            for (int dd = 0; dd < DT; dd++)
                acc[dd] = fmaf(part[0][dd][e], v, acc[dd]);
        }
#pragma unroll
        for (int dd = 0; dd < DT; dd++)
            c_out[(size_t)(b * TD + d0 + dd) * HH + tid] = acc[dd];
    }
}

// ---------------------------------------------------------------------------
// Launch: ortho -> (2x GEMM in one kernel) -> fused attention.
// Outputs: (c_outputs [B,TD,H], e_outputs [B,TD,TE]) back-to-back in d_out.
// ---------------------------------------------------------------------------
extern "C" void kernel_launch(void* const* d_in, const int* in_sizes, int n_in,
                              void* d_out, int out_size) {
    const float* enc = (const float*)d_in[0];
    const float* dec = (const float*)d_in[1];
    const float* Wa  = (const float*)d_in[2];
    const float* Ua  = (const float*)d_in[3];
    const float* Va  = (const float*)d_in[4];
    (void)in_sizes; (void)n_in;

    const int size_c = BB * TD * HH;   // 524288
    const int size_e = BB * TD * TE;   // 262144

    float* c_out;
    float* e_out;
    if (out_size >= size_c + size_e) {
        c_out = (float*)d_out;
        e_out = (float*)d_out + size_c;
    } else if (out_size == size_c) {
        c_out = (float*)d_out;
        e_out = nullptr;               // kernel redirects to g_dump
    } else {
        c_out = nullptr;
        e_out = (float*)d_out;
    }

    k_ortho<<<dim3(HH / 8, BB), 256>>>(enc);
    k_gemm<<<dim3(HH / 64, (BB * TE) / 64, 2), 256>>>(dec, Wa, Ua);
    k_attn<<<BB * (TD / DT), 256>>>(Va, c_out, e_out);
}

// round 14
// speedup vs baseline: 1.6088x; 1.0985x over previous
#include <cuda_runtime.h>
#include <cuda_bf16.h>
#include <math.h>

#define BB 16
#define TE 128
#define TD 128
#define HH 256

// Scratch (no allocation allowed -> __device__ globals)
__device__ float g_enc_o[BB * TE * HH];   // orthogonalized encoder [b][t][h]
__device__ float g_was[BB * TE * HH];     // enc_o @ W_a              [b][e][h]
__device__ float g_uah[BB * TD * HH];     // dec   @ U_a              [b][d][h]
__device__ float g_dump[BB * TD * HH];    // fallback sink if harness wants only one output

// ---------------------------------------------------------------------------
// K1: Gram-Schmidt-style ortho pass.
//   s[t] = sum_{j<t} x[j];  out = x - ((x*s)/(x*x))*x
// Warp owns one (b,h) column; lane owns 4 consecutive t. One 32-wide shfl
// scan of lane-sums (5 SHFLs) instead of 4 chained 32-scans (20 SHFLs).
// ---------------------------------------------------------------------------
__global__ void k_ortho(const float* __restrict__ enc) {
    const int b  = blockIdx.y;
    const int h0 = blockIdx.x * 8;
    const int tid = threadIdx.x;            // 256

    __shared__ float s[8][132];             // row stride 132 (16B-aligned, conflict-free)

    const float* src = enc + (size_t)b * TE * HH + h0;

#pragma unroll
    for (int i = 0; i < 4; i++) {
        int idx = tid + i * 256;
        int t = idx >> 3, hl = idx & 7;
        s[hl][t] = src[(size_t)t * HH + hl];
    }
    __syncthreads();

    const int w = tid >> 5, lane = tid & 31;
    {
        float4 v = *(const float4*)&s[w][4 * lane];
        // lane-local inclusive prefixes
        float i1 = v.x + v.y;
        float i2 = i1 + v.z;
        float i3 = i2 + v.w;
        // warp scan over lane sums
        float incl = i3;
#pragma unroll
        for (int off = 1; off < 32; off <<= 1) {
            float n = __shfl_up_sync(0xFFFFFFFFu, incl, off);
            if (lane >= off) incl += n;
        }
        float excl = incl - i3;             // sum over all t of lower lanes
        float4 o;
        {
            float st = excl;                 // t = 4*lane
            o.x = v.x - ((v.x * st) / (v.x * v.x)) * v.x;
        }
        {
            float st = excl + v.x;
            o.y = v.y - ((v.y * st) / (v.y * v.y)) * v.y;
        }
        {
            float st = excl + i1;
            o.z = v.z - ((v.z * st) / (v.z * v.z)) * v.z;
        }
        {
            float st = excl + i2;
            o.w = v.w - ((v.w * st) / (v.w * v.w)) * v.w;
        }
        *(float4*)&s[w][4 * lane] = o;
    }
    __syncthreads();

    float* dst = g_enc_o + (size_t)b * TE * HH + h0;
#pragma unroll
    for (int i = 0; i < 4; i++) {
        int idx = tid + i * 256;
        int t = idx >> 3, hl = idx & 7;
        dst[(size_t)t * HH + hl] = s[hl][t];
    }
}

// ---------------------------------------------------------------------------
// K2: two SGEMMs, C[2048,256] = A[2048,256] * W[256,256]  (plain FFMA)
//   z==0: was = enc_o @ W_a        z==1: uah = dec @ U_a
// 64x64 tile, BK=16, 256 threads, 4x4 microtile, k-major smem (vector LDS).
// ---------------------------------------------------------------------------
__global__ void k_gemm(const float* __restrict__ dec,
                       const float* __restrict__ Wa,
                       const float* __restrict__ Ua) {
    const float* A;
    const float* W;
    float* C;
    if (blockIdx.z == 0) { A = g_enc_o; W = Wa; C = g_was; }
    else                 { A = dec;     W = Ua; C = g_uah; }

    __shared__ float As[16][64];   // [k][row]
    __shared__ float Bs[16][64];   // [k][col]

    const int tid = threadIdx.x;
    const int tx = tid & 15;        // col group
    const int ty = tid >> 4;        // row group
    const int row0 = blockIdx.y * 64;
    const int col0 = blockIdx.x * 64;

    const int ar = tid >> 2;          // 0..63 (row within tile)
    const int ak = (tid & 3) * 4;     // 0,4,8,12 (k offset)
    const int bk = tid >> 4;          // 0..15 (k row)
    const int bc = (tid & 15) * 4;    // 0..60 (col offset)

    float acc[4][4];
#pragma unroll
    for (int i = 0; i < 4; i++)
#pragma unroll
        for (int j = 0; j < 4; j++) acc[i][j] = 0.0f;

    for (int kk = 0; kk < HH; kk += 16) {
        float4 av = *(const float4*)&A[(size_t)(row0 + ar) * HH + kk + ak];
        float4 bv = *(const float4*)&W[(size_t)(kk + bk) * HH + col0 + bc];
        As[ak + 0][ar] = av.x;
        As[ak + 1][ar] = av.y;
        As[ak + 2][ar] = av.z;
        As[ak + 3][ar] = av.w;
        *(float4*)&Bs[bk][bc] = bv;
        __syncthreads();

#pragma unroll
        for (int k = 0; k < 16; k++) {
            float4 a = *(const float4*)&As[k][ty * 4];
            float4 b = *(const float4*)&Bs[k][tx * 4];
            acc[0][0] = fmaf(a.x, b.x, acc[0][0]);
            acc[0][1] = fmaf(a.x, b.y, acc[0][1]);
            acc[0][2] = fmaf(a.x, b.z, acc[0][2]);
            acc[0][3] = fmaf(a.x, b.w, acc[0][3]);
            acc[1][0] = fmaf(a.y, b.x, acc[1][0]);
            acc[1][1] = fmaf(a.y, b.y, acc[1][1]);
            acc[1][2] = fmaf(a.y, b.z, acc[1][2]);
            acc[1][3] = fmaf(a.y, b.w, acc[1][3]);
            acc[2][0] = fmaf(a.z, b.x, acc[2][0]);
            acc[2][1] = fmaf(a.z, b.y, acc[2][1]);
            acc[2][2] = fmaf(a.z, b.z, acc[2][2]);
            acc[2][3] = fmaf(a.z, b.w, acc[2][3]);
            acc[3][0] = fmaf(a.w, b.x, acc[3][0]);
            acc[3][1] = fmaf(a.w, b.y, acc[3][1]);
            acc[3][2] = fmaf(a.w, b.z, acc[3][2]);
            acc[3][3] = fmaf(a.w, b.w, acc[3][3]);
        }
        __syncthreads();
    }

#pragma unroll
    for (int i = 0; i < 4; i++) {
        float4 v = make_float4(acc[i][0], acc[i][1], acc[i][2], acc[i][3]);
        *(float4*)&C[(size_t)(row0 + ty * 4 + i) * HH + col0 + tx * 4] = v;
    }
}

// ---------------------------------------------------------------------------
// K3: fused energy -> softmax -> context.  256 threads = 8 warps, DT=8.
// Warp w owns decoder row d0+w. Lane owns h in {4l..4l+3, 128+4l..128+4l+3}
// -> u and V live in 16 REGISTERS per lane (zero LDS for them); per e the
// warp does only 2 contiguous LDS.128 from the staged was tile (conflict-
// free), then 8x {FADD, tanh(MUFU), FFMA} and a 5-shfl butterfly.
// Energies land in registers already in softmax layout (e = ec*32 + lane).
//   energy[d][e] = sum_h tanh(was[b,e,h] + uah[b,d,h]) * V[h]
// ---------------------------------------------------------------------------
#define DT 8
#define EC 32

__global__ void __launch_bounds__(256, 4) k_attn(const float* __restrict__ Va,
                                                 float* __restrict__ c_out_p,
                                                 float* __restrict__ e_out_p) {
    float* c_out = c_out_p ? c_out_p : g_dump;
    float* e_out = e_out_p ? e_out_p : g_dump;

    const int b = blockIdx.x >> 4;          // / (TD/DT = 16)
    const int d0 = (blockIdx.x & 15) * DT;
    const int tid = threadIdx.x;            // 256 threads

    __shared__ float was_s[EC][HH];         // 32 KB staged e-tile
    __shared__ float p_s[DT][TE];           // 4 KB probabilities

    const int w = tid >> 5;                 // warp -> decoder row
    const int lane = tid & 31;
    const int d = d0 + w;

    // u, V register-resident: lane's h-set = {4l..4l+3} U {128+4l..+3}
    const float4 u0 = *(const float4*)&g_uah[(size_t)(b * TD + d) * HH + 4 * lane];
    const float4 u1 = *(const float4*)&g_uah[(size_t)(b * TD + d) * HH + 128 + 4 * lane];
    const float4 v0 = *(const float4*)&Va[4 * lane];
    const float4 v1 = *(const float4*)&Va[128 + 4 * lane];

    float pe[4];                            // energy for e = ec*32 + lane

#pragma unroll
    for (int ec = 0; ec < TE / EC; ec++) {
        // stage was[b, ec*32 .. +32, :]: 2048 float4s, 8 per thread, coalesced
#pragma unroll
        for (int i = 0; i < 8; i++) {
            int idx = tid + i * 256;        // float4 index
            int e = idx >> 6;
            int c = (idx & 63) * 4;
            *(float4*)&was_s[e][c] =
                *(const float4*)&g_was[(size_t)(b * TE + ec * EC + e) * HH + c];
        }
        __syncthreads();

#pragma unroll 4
        for (int e = 0; e < EC; e++) {
            float4 a0 = *(const float4*)&was_s[e][4 * lane];
            float4 a1 = *(const float4*)&was_s[e][128 + 4 * lane];
            float acc = 0.0f;
            float x, th;
            x = a0.x + u0.x; asm("tanh.approx.f32 %0, %1;" : "=f"(th) : "f"(x)); acc = fmaf(th, v0.x, acc);
            x = a0.y + u0.y; asm("tanh.approx.f32 %0, %1;" : "=f"(th) : "f"(x)); acc = fmaf(th, v0.y, acc);
            x = a0.z + u0.z; asm("tanh.approx.f32 %0, %1;" : "=f"(th) : "f"(x)); acc = fmaf(th, v0.z, acc);
            x = a0.w + u0.w; asm("tanh.approx.f32 %0, %1;" : "=f"(th) : "f"(x)); acc = fmaf(th, v0.w, acc);
            x = a1.x + u1.x; asm("tanh.approx.f32 %0, %1;" : "=f"(th) : "f"(x)); acc = fmaf(th, v1.x, acc);
            x = a1.y + u1.y; asm("tanh.approx.f32 %0, %1;" : "=f"(th) : "f"(x)); acc = fmaf(th, v1.y, acc);
            x = a1.z + u1.z; asm("tanh.approx.f32 %0, %1;" : "=f"(th) : "f"(x)); acc = fmaf(th, v1.z, acc);
            x = a1.w + u1.w; asm("tanh.approx.f32 %0, %1;" : "=f"(th) : "f"(x)); acc = fmaf(th, v1.w, acc);
            // butterfly: all lanes get the full h-sum
#pragma unroll
            for (int off = 16; off > 0; off >>= 1)
                acc += __shfl_xor_sync(0xFFFFFFFFu, acc, off);
            if (lane == e) pe[ec] = acc;
        }
        __syncthreads();
    }

    // softmax over 128 energies held as pe[0..3] across 32 lanes (per warp)
    {
        float m = fmaxf(fmaxf(pe[0], pe[1]), fmaxf(pe[2], pe[3]));
#pragma unroll
        for (int off = 16; off > 0; off >>= 1)
            m = fmaxf(m, __shfl_xor_sync(0xFFFFFFFFu, m, off));
        float s = 0.0f;
#pragma unroll
        for (int j = 0; j < 4; j++) { pe[j] = __expf(pe[j] - m); s += pe[j]; }
#pragma unroll
        for (int off = 16; off > 0; off >>= 1)
            s += __shfl_xor_sync(0xFFFFFFFFu, s, off);
        float inv = 1.0f / s;
#pragma unroll
        for (int j = 0; j < 4; j++) {
            float p = pe[j] * inv;
            p_s[w][j * 32 + lane] = p;
            e_out[(size_t)(b * TD + d) * TE + j * 32 + lane] = p;
        }
    }
    __syncthreads();

    // context: thread owns column h = tid; 8 decoder-row accumulators
    {
        float acc[DT];
#pragma unroll
        for (int dd = 0; dd < DT; dd++) acc[dd] = 0.0f;
        const float* encb = g_enc_o + (size_t)b * TE * HH;
#pragma unroll 2
        for (int e = 0; e < TE; e += 4) {
            float x0 = encb[(size_t)(e + 0) * HH + tid];
            float x1 = encb[(size_t)(e + 1) * HH + tid];
            float x2 = encb[(size_t)(e + 2) * HH + tid];
            float x3 = encb[(size_t)(e + 3) * HH + tid];
#pragma unroll
            for (int dd = 0; dd < DT; dd++) {
                float4 p = *(const float4*)&p_s[dd][e];
                float a = acc[dd];
                a = fmaf(p.x, x0, a);
                a = fmaf(p.y, x1, a);
                a = fmaf(p.z, x2, a);
                a = fmaf(p.w, x3, a);
                acc[dd] = a;
            }
        }
#pragma unroll
        for (int dd = 0; dd < DT; dd++)
            c_out[(size_t)(b * TD + d0 + dd) * HH + tid] = acc[dd];
    }
}

// ---------------------------------------------------------------------------
// Launch: ortho -> (2x GEMM in one kernel) -> fused attention.
// Outputs: (c_outputs [B,TD,H], e_outputs [B,TD,TE]) back-to-back in d_out.
// ---------------------------------------------------------------------------
extern "C" void kernel_launch(void* const* d_in, const int* in_sizes, int n_in,
                              void* d_out, int out_size) {
    const float* enc = (const float*)d_in[0];
    const float* dec = (const float*)d_in[1];
    const float* Wa  = (const float*)d_in[2];
    const float* Ua  = (const float*)d_in[3];
    const float* Va  = (const float*)d_in[4];
    (void)in_sizes; (void)n_in;

    const int size_c = BB * TD * HH;   // 524288
    const int size_e = BB * TD * TE;   // 262144

    float* c_out;
    float* e_out;
    if (out_size >= size_c + size_e) {
        c_out = (float*)d_out;
        e_out = (float*)d_out + size_c;
    } else if (out_size == size_c) {
        c_out = (float*)d_out;
        e_out = nullptr;               // kernel redirects to g_dump
    } else {
        c_out = nullptr;
        e_out = (float*)d_out;
    }

    k_ortho<<<dim3(HH / 8, BB), 256>>>(enc);
    k_gemm<<<dim3(HH / 64, (BB * TE) / 64, 2), 256>>>(dec, Wa, Ua);
    k_attn<<<BB * (TD / DT), 256>>>(Va, c_out, e_out);
}

// round 17
// speedup vs baseline: 1.8048x; 1.1218x over previous
#include <cuda_runtime.h>
#include <cuda_bf16.h>
#include <math.h>

#define BB 16
#define TE 128
#define TD 128
#define HH 256

// Scratch (no allocation allowed -> __device__ globals)
__device__ float g_enc_o[BB * TE * HH];   // orthogonalized encoder [b][t][h]
__device__ float g_was[BB * TE * HH];     // enc_o @ W_a              [b][e][h]
__device__ float g_uah[BB * TD * HH];     // dec   @ U_a              [b][d][h]
__device__ float g_dump[BB * TD * HH];    // fallback sink if harness wants only one output

// ---------------------------------------------------------------------------
// K1: Gram-Schmidt-style ortho pass (unchanged, 5.7us).
// ---------------------------------------------------------------------------
__global__ void k_ortho(const float* __restrict__ enc) {
    const int b  = blockIdx.y;
    const int h0 = blockIdx.x * 8;
    const int tid = threadIdx.x;            // 256

    __shared__ float s[8][132];             // row stride 132 (16B-aligned, conflict-free)

    const float* src = enc + (size_t)b * TE * HH + h0;

#pragma unroll
    for (int i = 0; i < 4; i++) {
        int idx = tid + i * 256;
        int t = idx >> 3, hl = idx & 7;
        s[hl][t] = src[(size_t)t * HH + hl];
    }
    __syncthreads();

    const int w = tid >> 5, lane = tid & 31;
    {
        float4 v = *(const float4*)&s[w][4 * lane];
        float i1 = v.x + v.y;
        float i2 = i1 + v.z;
        float i3 = i2 + v.w;
        float incl = i3;
#pragma unroll
        for (int off = 1; off < 32; off <<= 1) {
            float n = __shfl_up_sync(0xFFFFFFFFu, incl, off);
            if (lane >= off) incl += n;
        }
        float excl = incl - i3;
        float4 o;
        { float st = excl;        o.x = v.x - ((v.x * st) / (v.x * v.x)) * v.x; }
        { float st = excl + v.x;  o.y = v.y - ((v.y * st) / (v.y * v.y)) * v.y; }
        { float st = excl + i1;   o.z = v.z - ((v.z * st) / (v.z * v.z)) * v.z; }
        { float st = excl + i2;   o.w = v.w - ((v.w * st) / (v.w * v.w)) * v.w; }
        *(float4*)&s[w][4 * lane] = o;
    }
    __syncthreads();

    float* dst = g_enc_o + (size_t)b * TE * HH + h0;
#pragma unroll
    for (int i = 0; i < 4; i++) {
        int idx = tid + i * 256;
        int t = idx >> 3, hl = idx & 7;
        dst[(size_t)t * HH + hl] = s[hl][t];
    }
}

// ---------------------------------------------------------------------------
// K2: two SGEMMs on TENSOR CORES — mma.sync.m16n8k8 TF32, 3xTF32 split
// precision (acc += Ahi*Bhi + Ahi*Blo + Alo*Bhi) for fp32-grade accuracy.
//   z==0: was = enc_o @ W_a        z==1: uah = dec @ U_a
// Block tile 64x64, K-chunk 32; 8 warps as 2(m) x 4(n), warp tile 32x16.
// hi/lo computed ONCE at smem store via cvt.rna.tf32.f32.
// smem strides: A 36 (addr = 4*gid+tig mod 32, conflict-free),
//               B 72 (addr = 8*tig+gid mod 32, conflict-free).
// ---------------------------------------------------------------------------
__device__ __forceinline__ float tf32_rna(float f) {
    unsigned r;
    asm("cvt.rna.tf32.f32 %0, %1;" : "=r"(r) : "f"(f));
    return __uint_as_float(r);
}

#define MMA_TF32(d, a, b)                                                     \
    asm volatile(                                                             \
        "mma.sync.aligned.m16n8k8.row.col.f32.tf32.tf32.f32 "                 \
        "{%0,%1,%2,%3}, {%4,%5,%6,%7}, {%8,%9}, {%0,%1,%2,%3};"               \
        : "+f"((d)[0]), "+f"((d)[1]), "+f"((d)[2]), "+f"((d)[3])              \
        : "r"((a)[0]), "r"((a)[1]), "r"((a)[2]), "r"((a)[3]),                 \
          "r"((b)[0]), "r"((b)[1]))

__global__ void __launch_bounds__(256) k_gemm(const float* __restrict__ dec,
                                              const float* __restrict__ Wa,
                                              const float* __restrict__ Ua) {
    const float* A;
    const float* W;
    float* C;
    if (blockIdx.z == 0) { A = g_enc_o; W = Wa; C = g_was; }
    else                 { A = dec;     W = Ua; C = g_uah; }

    __shared__ float Ah[64][36], Al[64][36];   // 9KB + 9KB
    __shared__ float Bh[32][72], Bl[32][72];   // 9KB + 9KB

    const int tid = threadIdx.x;
    const int row0 = blockIdx.y * 64;
    const int col0 = blockIdx.x * 64;

    const int wid = tid >> 5, lane = tid & 31;
    const int gid = lane >> 2, tig = lane & 3;
    const int wm = (wid >> 2) * 32;     // 0 or 32
    const int wn = (wid & 3) * 16;      // 0,16,32,48

    float acc[2][2][4];
#pragma unroll
    for (int mi = 0; mi < 2; mi++)
#pragma unroll
        for (int ni = 0; ni < 2; ni++)
#pragma unroll
            for (int q = 0; q < 4; q++) acc[mi][ni][q] = 0.0f;

    const int arow = tid >> 3;          // 0..31 (+32 second iter)
    const int akq  = (tid & 7) * 4;     // 0..28
    const int brow = tid >> 4;          // 0..15 (+16 second iter)
    const int bcq  = (tid & 15) * 4;    // 0..60

    for (int k0 = 0; k0 < HH; k0 += 32) {
        // stage A 64x32 (hi/lo)
#pragma unroll
        for (int it = 0; it < 2; it++) {
            int r = arow + it * 32;
            float4 v = *(const float4*)&A[(size_t)(row0 + r) * HH + k0 + akq];
            float hx = tf32_rna(v.x), hy = tf32_rna(v.y);
            float hz = tf32_rna(v.z), hw = tf32_rna(v.w);
            *(float4*)&Ah[r][akq] = make_float4(hx, hy, hz, hw);
            *(float4*)&Al[r][akq] = make_float4(
                tf32_rna(v.x - hx), tf32_rna(v.y - hy),
                tf32_rna(v.z - hz), tf32_rna(v.w - hw));
        }
        // stage B 32x64 (hi/lo)
#pragma unroll
        for (int it = 0; it < 2; it++) {
            int r = brow + it * 16;
            float4 v = *(const float4*)&W[(size_t)(k0 + r) * HH + col0 + bcq];
            float hx = tf32_rna(v.x), hy = tf32_rna(v.y);
            float hz = tf32_rna(v.z), hw = tf32_rna(v.w);
            *(float4*)&Bh[r][bcq] = make_float4(hx, hy, hz, hw);
            *(float4*)&Bl[r][bcq] = make_float4(
                tf32_rna(v.x - hx), tf32_rna(v.y - hy),
                tf32_rna(v.z - hz), tf32_rna(v.w - hw));
        }
        __syncthreads();

#pragma unroll
        for (int kk = 0; kk < 32; kk += 8) {
            unsigned ah[2][4], al[2][4], bh[2][2], bl[2][2];
#pragma unroll
            for (int mi = 0; mi < 2; mi++) {
                int r = wm + mi * 16 + gid;
                ah[mi][0] = __float_as_uint(Ah[r][kk + tig]);
                ah[mi][1] = __float_as_uint(Ah[r + 8][kk + tig]);
                ah[mi][2] = __float_as_uint(Ah[r][kk + tig + 4]);
                ah[mi][3] = __float_as_uint(Ah[r + 8][kk + tig + 4]);
                al[mi][0] = __float_as_uint(Al[r][kk + tig]);
                al[mi][1] = __float_as_uint(Al[r + 8][kk + tig]);
                al[mi][2] = __float_as_uint(Al[r][kk + tig + 4]);
                al[mi][3] = __float_as_uint(Al[r + 8][kk + tig + 4]);
            }
#pragma unroll
            for (int ni = 0; ni < 2; ni++) {
                int c = wn + ni * 8 + gid;
                bh[ni][0] = __float_as_uint(Bh[kk + tig][c]);
                bh[ni][1] = __float_as_uint(Bh[kk + tig + 4][c]);
                bl[ni][0] = __float_as_uint(Bl[kk + tig][c]);
                bl[ni][1] = __float_as_uint(Bl[kk + tig + 4][c]);
            }
#pragma unroll
            for (int mi = 0; mi < 2; mi++)
#pragma unroll
                for (int ni = 0; ni < 2; ni++) {
                    MMA_TF32(acc[mi][ni], ah[mi], bh[ni]);
                    MMA_TF32(acc[mi][ni], ah[mi], bl[ni]);
                    MMA_TF32(acc[mi][ni], al[mi], bh[ni]);
                }
        }
        __syncthreads();
    }

    // epilogue: c0,c1 contiguous cols -> STG.64
#pragma unroll
    for (int mi = 0; mi < 2; mi++)
#pragma unroll
        for (int ni = 0; ni < 2; ni++) {
            int r = row0 + wm + mi * 16 + gid;
            int c = col0 + wn + ni * 8 + tig * 2;
            *(float2*)&C[(size_t)r * HH + c] =
                make_float2(acc[mi][ni][0], acc[mi][ni][1]);
            *(float2*)&C[(size_t)(r + 8) * HH + c] =
                make_float2(acc[mi][ni][2], acc[mi][ni][3]);
        }
}

// ---------------------------------------------------------------------------
// K3: fused energy -> softmax -> context (unchanged from R14).
// ---------------------------------------------------------------------------
#define DT 8
#define EC 32

__global__ void __launch_bounds__(256, 4) k_attn(const float* __restrict__ Va,
                                                 float* __restrict__ c_out_p,
                                                 float* __restrict__ e_out_p) {
    float* c_out = c_out_p ? c_out_p : g_dump;
    float* e_out = e_out_p ? e_out_p : g_dump;

    const int b = blockIdx.x >> 4;          // / (TD/DT = 16)
    const int d0 = (blockIdx.x & 15) * DT;
    const int tid = threadIdx.x;            // 256 threads

    __shared__ float was_s[EC][HH];         // 32 KB staged e-tile
    __shared__ float p_s[DT][TE];           // 4 KB probabilities

    const int w = tid >> 5;                 // warp -> decoder row
    const int lane = tid & 31;
    const int d = d0 + w;

    const float4 u0 = *(const float4*)&g_uah[(size_t)(b * TD + d) * HH + 4 * lane];
    const float4 u1 = *(const float4*)&g_uah[(size_t)(b * TD + d) * HH + 128 + 4 * lane];
    const float4 v0 = *(const float4*)&Va[4 * lane];
    const float4 v1 = *(const float4*)&Va[128 + 4 * lane];

    float pe[4];

#pragma unroll
    for (int ec = 0; ec < TE / EC; ec++) {
#pragma unroll
        for (int i = 0; i < 8; i++) {
            int idx = tid + i * 256;
            int e = idx >> 6;
            int c = (idx & 63) * 4;
            *(float4*)&was_s[e][c] =
                *(const float4*)&g_was[(size_t)(b * TE + ec * EC + e) * HH + c];
        }
        __syncthreads();

#pragma unroll 4
        for (int e = 0; e < EC; e++) {
            float4 a0 = *(const float4*)&was_s[e][4 * lane];
            float4 a1 = *(const float4*)&was_s[e][128 + 4 * lane];
            float acc = 0.0f;
            float x, th;
            x = a0.x + u0.x; asm("tanh.approx.f32 %0, %1;" : "=f"(th) : "f"(x)); acc = fmaf(th, v0.x, acc);
            x = a0.y + u0.y; asm("tanh.approx.f32 %0, %1;" : "=f"(th) : "f"(x)); acc = fmaf(th, v0.y, acc);
            x = a0.z + u0.z; asm("tanh.approx.f32 %0, %1;" : "=f"(th) : "f"(x)); acc = fmaf(th, v0.z, acc);
            x = a0.w + u0.w; asm("tanh.approx.f32 %0, %1;" : "=f"(th) : "f"(x)); acc = fmaf(th, v0.w, acc);
            x = a1.x + u1.x; asm("tanh.approx.f32 %0, %1;" : "=f"(th) : "f"(x)); acc = fmaf(th, v1.x, acc);
            x = a1.y + u1.y; asm("tanh.approx.f32 %0, %1;" : "=f"(th) : "f"(x)); acc = fmaf(th, v1.y, acc);
            x = a1.z + u1.z; asm("tanh.approx.f32 %0, %1;" : "=f"(th) : "f"(x)); acc = fmaf(th, v1.z, acc);
            x = a1.w + u1.w; asm("tanh.approx.f32 %0, %1;" : "=f"(th) : "f"(x)); acc = fmaf(th, v1.w, acc);
#pragma unroll
            for (int off = 16; off > 0; off >>= 1)
                acc += __shfl_xor_sync(0xFFFFFFFFu, acc, off);
            if (lane == e) pe[ec] = acc;
        }
        __syncthreads();
    }

    {
        float m = fmaxf(fmaxf(pe[0], pe[1]), fmaxf(pe[2], pe[3]));
#pragma unroll
        for (int off = 16; off > 0; off >>= 1)
            m = fmaxf(m, __shfl_xor_sync(0xFFFFFFFFu, m, off));
        float s = 0.0f;
#pragma unroll
        for (int j = 0; j < 4; j++) { pe[j] = __expf(pe[j] - m); s += pe[j]; }
#pragma unroll
        for (int off = 16; off > 0; off >>= 1)
            s += __shfl_xor_sync(0xFFFFFFFFu, s, off);
        float inv = 1.0f / s;
#pragma unroll
        for (int j = 0; j < 4; j++) {
            float p = pe[j] * inv;
            p_s[w][j * 32 + lane] = p;
            e_out[(size_t)(b * TD + d) * TE + j * 32 + lane] = p;
        }
    }
    __syncthreads();

    {
        float acc[DT];
#pragma unroll
        for (int dd = 0; dd < DT; dd++) acc[dd] = 0.0f;
        const float* encb = g_enc_o + (size_t)b * TE * HH;
#pragma unroll 2
        for (int e = 0; e < TE; e += 4) {
            float x0 = encb[(size_t)(e + 0) * HH + tid];
            float x1 = encb[(size_t)(e + 1) * HH + tid];
            float x2 = encb[(size_t)(e + 2) * HH + tid];
            float x3 = encb[(size_t)(e + 3) * HH + tid];
#pragma unroll
            for (int dd = 0; dd < DT; dd++) {
                float4 p = *(const float4*)&p_s[dd][e];
                float a = acc[dd];
                a = fmaf(p.x, x0, a);
                a = fmaf(p.y, x1, a);
                a = fmaf(p.z, x2, a);
                a = fmaf(p.w, x3, a);
                acc[dd] = a;
            }
        }
#pragma unroll
        for (int dd = 0; dd < DT; dd++)
            c_out[(size_t)(b * TD + d0 + dd) * HH + tid] = acc[dd];
    }
}

// ---------------------------------------------------------------------------
// Launch: ortho -> (2x TF32 GEMM in one kernel) -> fused attention.
// Outputs: (c_outputs [B,TD,H], e_outputs [B,TD,TE]) back-to-back in d_out.
// ---------------------------------------------------------------------------
extern "C" void kernel_launch(void* const* d_in, const int* in_sizes, int n_in,
                              void* d_out, int out_size) {
    const float* enc = (const float*)d_in[0];
    const float* dec = (const float*)d_in[1];
    const float* Wa  = (const float*)d_in[2];
    const float* Ua  = (const float*)d_in[3];
    const float* Va  = (const float*)d_in[4];
    (void)in_sizes; (void)n_in;

    const int size_c = BB * TD * HH;   // 524288
    const int size_e = BB * TD * TE;   // 262144

    float* c_out;
    float* e_out;
    if (out_size >= size_c + size_e) {
        c_out = (float*)d_out;
        e_out = (float*)d_out + size_c;
    } else if (out_size == size_c) {
        c_out = (float*)d_out;
        e_out = nullptr;               // kernel redirects to g_dump
    } else {
        c_out = nullptr;
        e_out = (float*)d_out;
    }

    k_ortho<<<dim3(HH / 8, BB), 256>>>(enc);
    k_gemm<<<dim3(HH / 64, (BB * TE) / 64, 2), 256>>>(dec, Wa, Ua);
    k_attn<<<BB * (TD / DT), 256>>>(Va, c_out, e_out);
}